// round 9
// baseline (speedup 1.0000x reference)
#include <cuda_runtime.h>
#include <cuda_bf16.h>

// Problem constants
#define T_STEPS 2048
#define BATCH   512
#define INPUT   42
#define HIDDEN  64
#define GATES   (4 * HIDDEN)   // 256
#define OUT_DIM 2
#define SCAN_THREADS 256       // 8 warps (best measured config)

// xproj scratch, padded by 4 timesteps so prefetch needs no bounds check.
__device__ float g_xproj[(T_STEPS + 4) * GATES];
// All hidden states h(t): (T, 64) = 512 KB.
__device__ float g_hbuf[T_STEPS * HIDDEN];

// Packed f32x2 ops (Blackwell FFMA2 — only reachable via PTX)
#define FMA2(acc, a, b) asm("fma.rn.f32x2 %0, %1, %2, %0;" : "+l"(acc) : "l"(a), "l"(b))
#define ADD2(d, a, b)   asm("add.rn.f32x2 %0, %1, %2;" : "=l"(d) : "l"(a), "l"(b))
#define TANHA(d, a)     asm("tanh.approx.f32 %0, %1;" : "=f"(d) : "f"(a))
#define PACK2(d, lo, hi) asm("mov.b64 %0, {%1, %2};" : "=l"(d) : "f"(lo), "f"(hi))
#define UNPACK2(lo, hi, s) asm("mov.b64 {%0, %1}, %2;" : "=f"(lo), "=f"(hi) : "l"(s))

// ---------------------------------------------------------------------------
// Kernel 1: x_proj[t, g] = dot(x[t, 511, :], W_ih[g, :]) + b_ih[g] + b_hh[g]
// ---------------------------------------------------------------------------
__global__ void xproj_kernel(const float* __restrict__ x,
                             const float* __restrict__ Wih,
                             const float* __restrict__ bih,
                             const float* __restrict__ bhh)
{
    __shared__ __align__(16) float xs[INPUT];
    const int t = blockIdx.x;
    const int j = threadIdx.x;

    if (j < INPUT) {
        xs[j] = x[((size_t)t * BATCH + (BATCH - 1)) * INPUT + j];
    }
    __syncthreads();

    float acc = bih[j] + bhh[j];
    const float* wr = Wih + j * INPUT;
#pragma unroll
    for (int k = 0; k < INPUT; k++) {
        acc = fmaf(xs[k], __ldg(&wr[k]), acc);
    }
    g_xproj[t * GATES + j] = acc;
}

// ---------------------------------------------------------------------------
// Kernel 2: sequential LSTM scan. One block, 8 warps, 1 barrier per step.
// Warp w owns units [8w, 8w+8). Lane l computes gate (l>>3) of unit 8w+(l&7).
// Gate exchange: 4 index shuffles. All lanes redundantly update c (4 replicas
// per unit) -> branch-free; only two predicated stores, on DIFFERENT lanes
// (STS: lanes 0-7, STG: lanes 8-15) to keep the shared-store path minimal.
// Activations: HW tanh.approx (sigmoid via 0.5*tanh(x/2)+0.5).
// xp is folded into the FFMA2 accumulator init (no tail adds on the chain).
// ---------------------------------------------------------------------------
__global__ void __launch_bounds__(SCAN_THREADS, 1)
lstm_scan_kernel(const float* __restrict__ Whh)
{
    __shared__ __align__(16) float h_sh[2][HIDDEN];

    const int j    = threadIdx.x;
    const int w    = j >> 5;
    const int l    = j & 31;
    const int gate = l >> 3;                // 0=i,1=f,2=g,3=o
    const int u8   = l & 7;
    const int unit = (w << 3) + u8;         // 0..63
    const int row  = gate * HIDDEN + unit;  // row in W_hh / col in xproj

    // W_hh row in registers, packed as f32x2 pairs (32 x u64)
    unsigned long long wreg[32];
    {
        const ulonglong2* wp = reinterpret_cast<const ulonglong2*>(Whh + row * HIDDEN);
#pragma unroll
        for (int k = 0; k < 16; k++) {
            ulonglong2 v = wp[k];
            wreg[2 * k]     = v.x;
            wreg[2 * k + 1] = v.y;
        }
    }

    // Activation affine params: g-gate = tanh; i,f,o = 0.5*tanh(0.5x)+0.5
    const bool  is_g = (gate == 2);
    const float s1   = is_g ? 1.0f : 0.5f;
    const float s3   = is_g ? 0.0f : 0.5f;

    if (j < HIDDEN) { h_sh[0][j] = 0.0f; h_sh[1][j] = 0.0f; }
    float c = 0.0f;   // replicated across the 4 gate-lanes of a unit

    // xproj software pipeline, distance 2 (rows T..T+3 are padding)
    float xp0 = g_xproj[row];
    float xp1 = g_xproj[GATES + row];
    __syncthreads();

#pragma unroll 2
    for (int t = 0; t < T_STEPS; t++) {
        float xp_pre = g_xproj[(t + 2) * GATES + row];

        // dot(h, W_hh[row,:]): 32 FFMA2, 4 accumulators (chain 8 deep = 32cyc
        // < 64cyc issue wall). xp folded into a0's init -> no tail adds.
        const ulonglong2* hp = reinterpret_cast<const ulonglong2*>(h_sh[t & 1]);
        unsigned long long a0, a1 = 0, a2 = 0, a3 = 0;
        PACK2(a0, xp0, 0.0f);
#pragma unroll
        for (int k = 0; k < 16; k += 2) {
            ulonglong2 h0 = hp[k], h1 = hp[k + 1];
            FMA2(a0, h0.x, wreg[2 * k]);     FMA2(a1, h0.y, wreg[2 * k + 1]);
            FMA2(a2, h1.x, wreg[2 * k + 2]); FMA2(a3, h1.y, wreg[2 * k + 3]);
        }
        ADD2(a0, a0, a1); ADD2(a2, a2, a3); ADD2(a0, a0, a2);
        float lo, hi;
        UNPACK2(lo, hi, a0);
        float a = lo + hi;

        // Activation via HW tanh: v = s1 * tanh(s1 * a) + s3
        float th0, v;
        TANHA(th0, a * s1);
        v = fmaf(th0, s1, s3);

        // Gather all 4 gates of this lane's unit (4 independent shuffles)
        float iv = __shfl_sync(0xFFFFFFFFu, v, u8);
        float fv = __shfl_sync(0xFFFFFFFFu, v, u8 + 8);
        float gv = __shfl_sync(0xFFFFFFFFu, v, u8 + 16);
        float ov = __shfl_sync(0xFFFFFFFFu, v, u8 + 24);

        // Cell + hidden update (redundant in all lanes; branch-free)
        c = fmaf(fv, c, iv * gv);
        float th1;
        TANHA(th1, c);
        float hn = ov * th1;

        if (l < 8)             h_sh[(t + 1) & 1][unit] = hn;  // STS, lanes 0-7
        if (l >= 8 && l < 16)  g_hbuf[t * HIDDEN + unit] = hn; // STG, lanes 8-15
        __syncthreads();

        xp0 = xp1;
        xp1 = xp_pre;
    }
}

// ---------------------------------------------------------------------------
// Kernel 3: out[t, o] = dot(h(t), W_out[o,:]) + b_out[o]; fully parallel.
// ---------------------------------------------------------------------------
__global__ void out_kernel(const float* __restrict__ Wout,
                           const float* __restrict__ bout,
                           float* __restrict__ out)
{
    const int t = blockIdx.x;
    const int l = threadIdx.x;  // 32 threads
    const float* h = g_hbuf + t * HIDDEN;

    float h0 = h[l], h1 = h[l + 32];
    float p0 = fmaf(h0, Wout[l],          h1 * Wout[l + 32]);
    float p1 = fmaf(h0, Wout[HIDDEN + l], h1 * Wout[HIDDEN + l + 32]);
#pragma unroll
    for (int s = 16; s > 0; s >>= 1) {
        p0 += __shfl_xor_sync(0xFFFFFFFFu, p0, s);
        p1 += __shfl_xor_sync(0xFFFFFFFFu, p1, s);
    }
    if (l == 0) {
        out[t * OUT_DIM + 0] = p0 + bout[0];
        out[t * OUT_DIM + 1] = p1 + bout[1];
    }
}

// ---------------------------------------------------------------------------
// Launcher
// ---------------------------------------------------------------------------
extern "C" void kernel_launch(void* const* d_in, const int* in_sizes, int n_in,
                              void* d_out, int out_size)
{
    const float* x    = (const float*)d_in[0];  // (T, B, 42)
    const float* Wih  = (const float*)d_in[1];  // (256, 42)
    const float* Whh  = (const float*)d_in[2];  // (256, 64)
    const float* bih  = (const float*)d_in[3];  // (256,)
    const float* bhh  = (const float*)d_in[4];  // (256,)
    const float* Wout = (const float*)d_in[5];  // (2, 64)
    const float* bout = (const float*)d_in[6];  // (2,)
    float* out = (float*)d_out;                 // (T, 2)

    xproj_kernel<<<T_STEPS, GATES>>>(x, Wih, bih, bhh);
    lstm_scan_kernel<<<1, SCAN_THREADS>>>(Whh);
    out_kernel<<<T_STEPS, 32>>>(Wout, bout, out);
}

// round 10
// speedup vs baseline: 1.0007x; 1.0007x over previous
#include <cuda_runtime.h>
#include <cuda_bf16.h>

// Problem constants
#define T_STEPS 2048
#define BATCH   512
#define INPUT   42
#define HIDDEN  64
#define GATES   (4 * HIDDEN)   // 256
#define OUT_DIM 2
#define SCAN_THREADS 256       // 8 warps (best measured config)

// xproj scratch, padded by 4 timesteps so prefetch needs no bounds check.
__device__ float g_xproj[(T_STEPS + 4) * GATES];
// All hidden states h(t): (T, 64) = 512 KB.
__device__ float g_hbuf[T_STEPS * HIDDEN];

// Packed f32x2 ops (Blackwell FFMA2 — only reachable via PTX)
#define FMA2(acc, a, b) asm("fma.rn.f32x2 %0, %1, %2, %0;" : "+l"(acc) : "l"(a), "l"(b))
#define ADD2(d, a, b)   asm("add.rn.f32x2 %0, %1, %2;" : "=l"(d) : "l"(a), "l"(b))
#define TANHA(d, a)     asm("tanh.approx.f32 %0, %1;" : "=f"(d) : "f"(a))
#define PACK2(d, lo, hi) asm("mov.b64 %0, {%1, %2};" : "=l"(d) : "f"(lo), "f"(hi))
#define UNPACK2(lo, hi, s) asm("mov.b64 {%0, %1}, %2;" : "=f"(lo), "=f"(hi) : "l"(s))

// ---------------------------------------------------------------------------
// Kernel 1: x_proj[t, g] = dot(x[t, 511, :], W_ih[g, :]) + b_ih[g] + b_hh[g]
// ---------------------------------------------------------------------------
__global__ void xproj_kernel(const float* __restrict__ x,
                             const float* __restrict__ Wih,
                             const float* __restrict__ bih,
                             const float* __restrict__ bhh)
{
    __shared__ __align__(16) float xs[INPUT];
    const int t = blockIdx.x;
    const int j = threadIdx.x;

    if (j < INPUT) {
        xs[j] = x[((size_t)t * BATCH + (BATCH - 1)) * INPUT + j];
    }
    __syncthreads();

    float acc = bih[j] + bhh[j];
    const float* wr = Wih + j * INPUT;
#pragma unroll
    for (int k = 0; k < INPUT; k++) {
        acc = fmaf(xs[k], __ldg(&wr[k]), acc);
    }
    g_xproj[t * GATES + j] = acc;
}

// ---------------------------------------------------------------------------
// Kernel 2: sequential LSTM scan. One block, 8 warps, 1 barrier per step.
// Warp w owns units [8w, 8w+8). Lane l computes gate (l>>3) of unit 8w+(l&7).
// Gate exchange: 4 index shuffles. All lanes redundantly update c (4 replicas
// per unit) -> branch-free; only two predicated stores, on DIFFERENT lanes
// (STS: lanes 0-7, STG: lanes 8-15) to keep the shared-store path minimal.
// Activations: HW tanh.approx (sigmoid via 0.5*tanh(x/2)+0.5).
// xp is folded into the FFMA2 accumulator init (no tail adds on the chain).
// ---------------------------------------------------------------------------
__global__ void __launch_bounds__(SCAN_THREADS, 1)
lstm_scan_kernel(const float* __restrict__ Whh)
{
    __shared__ __align__(16) float h_sh[2][HIDDEN];

    const int j    = threadIdx.x;
    const int w    = j >> 5;
    const int l    = j & 31;
    const int gate = l >> 3;                // 0=i,1=f,2=g,3=o
    const int u8   = l & 7;
    const int unit = (w << 3) + u8;         // 0..63
    const int row  = gate * HIDDEN + unit;  // row in W_hh / col in xproj

    // W_hh row in registers, packed as f32x2 pairs (32 x u64)
    unsigned long long wreg[32];
    {
        const ulonglong2* wp = reinterpret_cast<const ulonglong2*>(Whh + row * HIDDEN);
#pragma unroll
        for (int k = 0; k < 16; k++) {
            ulonglong2 v = wp[k];
            wreg[2 * k]     = v.x;
            wreg[2 * k + 1] = v.y;
        }
    }

    // Activation affine params: g-gate = tanh; i,f,o = 0.5*tanh(0.5x)+0.5
    const bool  is_g = (gate == 2);
    const float s1   = is_g ? 1.0f : 0.5f;
    const float s3   = is_g ? 0.0f : 0.5f;

    if (j < HIDDEN) { h_sh[0][j] = 0.0f; h_sh[1][j] = 0.0f; }
    float c = 0.0f;   // replicated across the 4 gate-lanes of a unit

    // xproj software pipeline, distance 2 (rows T..T+3 are padding)
    float xp0 = g_xproj[row];
    float xp1 = g_xproj[GATES + row];
    __syncthreads();

#pragma unroll 2
    for (int t = 0; t < T_STEPS; t++) {
        float xp_pre = g_xproj[(t + 2) * GATES + row];

        // dot(h, W_hh[row,:]): 32 FFMA2, 4 accumulators (chain 8 deep = 32cyc
        // < 64cyc issue wall). xp folded into a0's init -> no tail adds.
        const ulonglong2* hp = reinterpret_cast<const ulonglong2*>(h_sh[t & 1]);
        unsigned long long a0, a1 = 0, a2 = 0, a3 = 0;
        PACK2(a0, xp0, 0.0f);
#pragma unroll
        for (int k = 0; k < 16; k += 2) {
            ulonglong2 h0 = hp[k], h1 = hp[k + 1];
            FMA2(a0, h0.x, wreg[2 * k]);     FMA2(a1, h0.y, wreg[2 * k + 1]);
            FMA2(a2, h1.x, wreg[2 * k + 2]); FMA2(a3, h1.y, wreg[2 * k + 3]);
        }
        ADD2(a0, a0, a1); ADD2(a2, a2, a3); ADD2(a0, a0, a2);
        float lo, hi;
        UNPACK2(lo, hi, a0);
        float a = lo + hi;

        // Activation via HW tanh: v = s1 * tanh(s1 * a) + s3
        float th0, v;
        TANHA(th0, a * s1);
        v = fmaf(th0, s1, s3);

        // Gather all 4 gates of this lane's unit (4 independent shuffles)
        float iv = __shfl_sync(0xFFFFFFFFu, v, u8);
        float fv = __shfl_sync(0xFFFFFFFFu, v, u8 + 8);
        float gv = __shfl_sync(0xFFFFFFFFu, v, u8 + 16);
        float ov = __shfl_sync(0xFFFFFFFFu, v, u8 + 24);

        // Cell + hidden update (redundant in all lanes; branch-free)
        c = fmaf(fv, c, iv * gv);
        float th1;
        TANHA(th1, c);
        float hn = ov * th1;

        if (l < 8)             h_sh[(t + 1) & 1][unit] = hn;  // STS, lanes 0-7
        if (l >= 8 && l < 16)  g_hbuf[t * HIDDEN + unit] = hn; // STG, lanes 8-15
        __syncthreads();

        xp0 = xp1;
        xp1 = xp_pre;
    }
}

// ---------------------------------------------------------------------------
// Kernel 3: out[t, o] = dot(h(t), W_out[o,:]) + b_out[o]; fully parallel.
// ---------------------------------------------------------------------------
__global__ void out_kernel(const float* __restrict__ Wout,
                           const float* __restrict__ bout,
                           float* __restrict__ out)
{
    const int t = blockIdx.x;
    const int l = threadIdx.x;  // 32 threads
    const float* h = g_hbuf + t * HIDDEN;

    float h0 = h[l], h1 = h[l + 32];
    float p0 = fmaf(h0, Wout[l],          h1 * Wout[l + 32]);
    float p1 = fmaf(h0, Wout[HIDDEN + l], h1 * Wout[HIDDEN + l + 32]);
#pragma unroll
    for (int s = 16; s > 0; s >>= 1) {
        p0 += __shfl_xor_sync(0xFFFFFFFFu, p0, s);
        p1 += __shfl_xor_sync(0xFFFFFFFFu, p1, s);
    }
    if (l == 0) {
        out[t * OUT_DIM + 0] = p0 + bout[0];
        out[t * OUT_DIM + 1] = p1 + bout[1];
    }
}

// ---------------------------------------------------------------------------
// Launcher
// ---------------------------------------------------------------------------
extern "C" void kernel_launch(void* const* d_in, const int* in_sizes, int n_in,
                              void* d_out, int out_size)
{
    const float* x    = (const float*)d_in[0];  // (T, B, 42)
    const float* Wih  = (const float*)d_in[1];  // (256, 42)
    const float* Whh  = (const float*)d_in[2];  // (256, 64)
    const float* bih  = (const float*)d_in[3];  // (256,)
    const float* bhh  = (const float*)d_in[4];  // (256,)
    const float* Wout = (const float*)d_in[5];  // (2, 64)
    const float* bout = (const float*)d_in[6];  // (2,)
    float* out = (float*)d_out;                 // (T, 2)

    xproj_kernel<<<T_STEPS, GATES>>>(x, Wih, bih, bhh);
    lstm_scan_kernel<<<1, SCAN_THREADS>>>(Whh);
    out_kernel<<<T_STEPS, 32>>>(Wout, bout, out);
}

// round 11
// speedup vs baseline: 1.2006x; 1.1998x over previous
#include <cuda_runtime.h>
#include <cuda_bf16.h>

// Problem constants
#define T_STEPS 2048
#define BATCH   512
#define INPUT   42
#define HIDDEN  64
#define GATES   (4 * HIDDEN)   // 256
#define OUT_DIM 2
#define SCAN_THREADS 128       // 4 warps = 1 per SMSP (no co-warp contention)

// xproj scratch, padded by 4 timesteps so prefetch needs no bounds check.
__device__ float g_xproj[(T_STEPS + 4) * GATES];
// All hidden states h(t): (T, 64) = 512 KB.
__device__ float g_hbuf[T_STEPS * HIDDEN];

// Packed f32x2 ops (Blackwell FFMA2 — only reachable via PTX)
#define FMA2(acc, a, b) asm("fma.rn.f32x2 %0, %1, %2, %0;" : "+l"(acc) : "l"(a), "l"(b))
#define ADD2(d, a, b)   asm("add.rn.f32x2 %0, %1, %2;" : "=l"(d) : "l"(a), "l"(b))
#define TANHA(d, a)     asm("tanh.approx.f32 %0, %1;" : "=f"(d) : "f"(a))
#define PACK2(d, lo, hi) asm("mov.b64 %0, {%1, %2};" : "=l"(d) : "f"(lo), "f"(hi))
#define UNPACK2(lo, hi, s) asm("mov.b64 {%0, %1}, %2;" : "=f"(lo), "=f"(hi) : "l"(s))

// ---------------------------------------------------------------------------
// Kernel 1: x_proj[t, g] = dot(x[t, 511, :], W_ih[g, :]) + b_ih[g] + b_hh[g]
// ---------------------------------------------------------------------------
__global__ void xproj_kernel(const float* __restrict__ x,
                             const float* __restrict__ Wih,
                             const float* __restrict__ bih,
                             const float* __restrict__ bhh)
{
    __shared__ __align__(16) float xs[INPUT];
    const int t = blockIdx.x;
    const int j = threadIdx.x;

    if (j < INPUT) {
        xs[j] = x[((size_t)t * BATCH + (BATCH - 1)) * INPUT + j];
    }
    __syncthreads();

    float acc = bih[j] + bhh[j];
    const float* wr = Wih + j * INPUT;
#pragma unroll
    for (int k = 0; k < INPUT; k++) {
        acc = fmaf(xs[k], __ldg(&wr[k]), acc);
    }
    g_xproj[t * GATES + j] = acc;
}

// ---------------------------------------------------------------------------
// Kernel 2: sequential LSTM scan. One block, 4 warps (1 per SMSP), 1 barrier
// per step.
//
// Warp w owns units [16w, 16w+16). Lane l owns a GATE PAIR of one unit:
//   unit = 16w + (l & 15); lanes 0-15 compute gates (i, f), lanes 16-31
//   compute gates (g, o) of the same unit. Both dots share the same h loads.
// Gate exchange: 2 parallel shfl.bfly(16) (partner lane holds the other two
// gates), then 2 FSELs. All lanes redundantly update c (2 replicas/unit):
// branch-free except two predicated stores.
// Activations: HW tanh.approx (sigmoid via 0.5*tanh(x/2)+0.5).
// xp folded into the FFMA2 accumulator inits (no tail adds on the chain).
// ---------------------------------------------------------------------------
__global__ void __launch_bounds__(SCAN_THREADS, 1)
lstm_scan_kernel(const float* __restrict__ Whh)
{
    __shared__ __align__(16) float h_sh[2][HIDDEN];

    const int j    = threadIdx.x;
    const int w    = j >> 5;
    const int l    = j & 31;
    const int u16  = l & 15;
    const int ps   = l >> 4;                       // 0: (i,f)  1: (g,o)
    const int unit = (w << 4) + u16;               // 0..63
    const int row0 = (ps * 2) * HIDDEN + unit;     // i or g
    const int row1 = (ps * 2 + 1) * HIDDEN + unit; // f or o

    // Two W_hh rows in registers, packed as f32x2 pairs (2 x 32 u64)
    unsigned long long wreg0[32], wreg1[32];
    {
        const ulonglong2* wp0 = reinterpret_cast<const ulonglong2*>(Whh + row0 * HIDDEN);
        const ulonglong2* wp1 = reinterpret_cast<const ulonglong2*>(Whh + row1 * HIDDEN);
#pragma unroll
        for (int k = 0; k < 16; k++) {
            ulonglong2 v0 = wp0[k];
            wreg0[2 * k] = v0.x;  wreg0[2 * k + 1] = v0.y;
            ulonglong2 v1 = wp1[k];
            wreg1[2 * k] = v1.x;  wreg1[2 * k + 1] = v1.y;
        }
    }

    // v0 activation: ps=0 -> sigmoid (i), ps=1 -> tanh (g).
    // v1 activation: always sigmoid (f or o).
    const float s1 = ps ? 1.0f : 0.5f;
    const float s3 = ps ? 0.0f : 0.5f;

    if (j < HIDDEN) { h_sh[0][j] = 0.0f; h_sh[1][j] = 0.0f; }
    float c = 0.0f;   // replicated across the 2 pair-lanes of a unit

    // xproj software pipeline, distance 2 (rows T..T+3 are padding)
    float xp0a = g_xproj[row0],         xp0b = g_xproj[row1];
    float xp1a = g_xproj[GATES + row0], xp1b = g_xproj[GATES + row1];
    __syncthreads();

#pragma unroll 2
    for (int t = 0; t < T_STEPS; t++) {
        float xpre_a = g_xproj[(t + 2) * GATES + row0];
        float xpre_b = g_xproj[(t + 2) * GATES + row1];

        // Two 64-dots over the same h: 64 FFMA2, 4 accumulators per row.
        // xp folded into the a0/b0 inits -> no tail adds on the chain.
        const ulonglong2* hp = reinterpret_cast<const ulonglong2*>(h_sh[t & 1]);
        unsigned long long a0, a1 = 0, a2 = 0, a3 = 0;
        unsigned long long b0, b1 = 0, b2 = 0, b3 = 0;
        PACK2(a0, xp0a, 0.0f);
        PACK2(b0, xp0b, 0.0f);
#pragma unroll
        for (int k = 0; k < 16; k += 2) {
            ulonglong2 h0 = hp[k], h1 = hp[k + 1];
            FMA2(a0, h0.x, wreg0[2 * k]);     FMA2(b0, h0.x, wreg1[2 * k]);
            FMA2(a1, h0.y, wreg0[2 * k + 1]); FMA2(b1, h0.y, wreg1[2 * k + 1]);
            FMA2(a2, h1.x, wreg0[2 * k + 2]); FMA2(b2, h1.x, wreg1[2 * k + 2]);
            FMA2(a3, h1.y, wreg0[2 * k + 3]); FMA2(b3, h1.y, wreg1[2 * k + 3]);
        }
        ADD2(a0, a0, a1); ADD2(a2, a2, a3); ADD2(a0, a0, a2);
        ADD2(b0, b0, b1); ADD2(b2, b2, b3); ADD2(b0, b0, b2);
        float alo, ahi, blo, bhi;
        UNPACK2(alo, ahi, a0);
        UNPACK2(blo, bhi, b0);
        float sa = alo + ahi;
        float sb = blo + bhi;

        // Activations (two independent MUFU tanh)
        float tha, thb, v0, v1;
        TANHA(tha, sa * s1);
        TANHA(thb, sb * 0.5f);
        v0 = fmaf(tha, s1, s3);           // i (ps0) or g (ps1)
        v1 = fmaf(thb, 0.5f, 0.5f);       // f (ps0) or o (ps1)

        // Exchange with the pair-partner lane (2 parallel butterflies)
        float o0 = __shfl_xor_sync(0xFFFFFFFFu, v0, 16);  // gv (ps0) / iv (ps1)
        float o1 = __shfl_xor_sync(0xFFFFFFFFu, v1, 16);  // ov (ps0) / fv (ps1)

        // iv*gv == v0*o0 in BOTH lane groups; fv/ov need a select.
        float fv = ps ? o1 : v1;
        float ov = ps ? v1 : o1;

        // Cell + hidden update (redundant in both pair-lanes; branch-free)
        c = fmaf(fv, c, v0 * o0);
        float thc;
        TANHA(thc, c);
        float hn = ov * thc;

        if (l < 16) h_sh[(t + 1) & 1][unit] = hn;   // STS: pair-lanes 0
        else        g_hbuf[t * HIDDEN + unit] = hn; // STG: pair-lanes 1
        __syncthreads();

        xp0a = xp1a; xp0b = xp1b;
        xp1a = xpre_a; xp1b = xpre_b;
    }
}

// ---------------------------------------------------------------------------
// Kernel 3: out[t, o] = dot(h(t), W_out[o,:]) + b_out[o]; fully parallel.
// ---------------------------------------------------------------------------
__global__ void out_kernel(const float* __restrict__ Wout,
                           const float* __restrict__ bout,
                           float* __restrict__ out)
{
    const int t = blockIdx.x;
    const int l = threadIdx.x;  // 32 threads
    const float* h = g_hbuf + t * HIDDEN;

    float h0 = h[l], h1 = h[l + 32];
    float p0 = fmaf(h0, Wout[l],          h1 * Wout[l + 32]);
    float p1 = fmaf(h0, Wout[HIDDEN + l], h1 * Wout[HIDDEN + l + 32]);
#pragma unroll
    for (int s = 16; s > 0; s >>= 1) {
        p0 += __shfl_xor_sync(0xFFFFFFFFu, p0, s);
        p1 += __shfl_xor_sync(0xFFFFFFFFu, p1, s);
    }
    if (l == 0) {
        out[t * OUT_DIM + 0] = p0 + bout[0];
        out[t * OUT_DIM + 1] = p1 + bout[1];
    }
}

// ---------------------------------------------------------------------------
// Launcher
// ---------------------------------------------------------------------------
extern "C" void kernel_launch(void* const* d_in, const int* in_sizes, int n_in,
                              void* d_out, int out_size)
{
    const float* x    = (const float*)d_in[0];  // (T, B, 42)
    const float* Wih  = (const float*)d_in[1];  // (256, 42)
    const float* Whh  = (const float*)d_in[2];  // (256, 64)
    const float* bih  = (const float*)d_in[3];  // (256,)
    const float* bhh  = (const float*)d_in[4];  // (256,)
    const float* Wout = (const float*)d_in[5];  // (2, 64)
    const float* bout = (const float*)d_in[6];  // (2,)
    float* out = (float*)d_out;                 // (T, 2)

    xproj_kernel<<<T_STEPS, GATES>>>(x, Wih, bih, bhh);
    lstm_scan_kernel<<<1, SCAN_THREADS>>>(Whh);
    out_kernel<<<T_STEPS, 32>>>(Wout, bout, out);
}